// round 8
// baseline (speedup 1.0000x reference)
#include <cuda_runtime.h>
#include <math_constants.h>

#define BB 512
#define SS 200
#define UU 50
#define DD 32
#define NITER 13          // ceil(50 rows / 4 rows-per-iter)
#define TPW 4             // tiles per warp (persistent, grid-stride)
#define NEG_INF_V (-1e9f)

__global__ __launch_bounds__(256)
void DIB_attn_kernel(const float* __restrict__ cur_user,   // [B, D]
                     const float* __restrict__ sim_user,   // [B, S, U, D]
                     const float* __restrict__ cur_item,   // [B, S, D]
                     const int* __restrict__ mask,          // [B, S, U] (bool -> int32)
                     float* __restrict__ out)               // [B, S, D]
{
    const unsigned FULL = 0xffffffffu;
    const int NW = (BB * SS) / TPW;                     // 25600 concurrent warps
    int gw = (blockIdx.x * blockDim.x + threadIdx.x) >> 5;
    if (gw >= NW) return;
    int lane = threadIdx.x & 31;
    int sub  = lane >> 3;       // 0..3 : row within 4-row group
    int quad = lane & 7;        // 0..7 : dims quad*4 .. quad*4+3

    // ---- Prefetch mask for the first tile (only exposed round-trip) ----
    int tile_id = gw;
    long long mb = (long long)tile_id * UU;
    int m0 = __ldg(mask + mb + lane);
    int m1 = (lane + 32 < UU) ? __ldg(mask + mb + 32 + lane) : 1;

    #pragma unroll 1
    for (int t = 0; t < TPW; t++) {
        int next_id = tile_id + NW;

        // ---- Issue next tile's mask loads NOW; first use is ~250 instrs away ----
        int nm0 = 0, nm1 = 1;
        if (t + 1 < TPW) {
            long long nmb = (long long)next_id * UU;
            nm0 = __ldg(mask + nmb + lane);
            nm1 = (lane + 32 < UU) ? __ldg(mask + nmb + 32 + lane) : 1;
        }

        // ---- Bitmap from already-arrived mask ----
        unsigned bits0 = __ballot_sync(FULL, m0 == 0);
        unsigned bits1 = __ballot_sync(FULL, (lane + 32 < UU) && (m1 == 0));
        bool degen = (bits0 | bits1) == 0u;             // all masked -> uniform

        int b = tile_id / SS;
        float4 cu = __ldg((const float4*)(cur_user + b * DD) + quad);
        const float* tile = sim_user + (long long)tile_id * (UU * DD);

        // ---- Predicated tile load: masked rows fetch NOTHING (their 128B
        //      line is owned by 8 lanes; predicated-off LDG = no request).
        //      Predicates computed ONCE, reused in the score pass.
        float4 v[NITER];
        bool   un[NITER];
        #pragma unroll
        for (int i = 0; i < NITER; i++) {
            int u = i * 4 + sub;
            bool inb = (u < UU);
            un[i] = inb &&
                (((u < 32 ? (bits0 >> u) : (bits1 >> (u - 32))) & 1u) != 0u);
            float4 vv = make_float4(0.f, 0.f, 0.f, 0.f);
            if (inb && (un[i] || degen))
                vv = __ldg((const float4*)(tile + u * DD) + quad);
            v[i] = vv;
        }

        // ---- Dot products + scores (masked -> -1e9, pad -> -inf) ----
        float sc[NITER];
        #pragma unroll
        for (int i = 0; i < NITER; i++) {
            int u = i * 4 + sub;
            float p = v[i].x * cu.x + v[i].y * cu.y + v[i].z * cu.z + v[i].w * cu.w;
            p += __shfl_xor_sync(FULL, p, 1);
            p += __shfl_xor_sync(FULL, p, 2);
            p += __shfl_xor_sync(FULL, p, 4);           // 8-lane group holds score
            sc[i] = (u < UU) ? (un[i] ? p : NEG_INF_V) : -CUDART_INF_F;
        }

        // ---- Softmax over all 50 (masked rows -> weight exactly 0; degen:
        //      all sc=-1e9 -> uniform 1/50 over fully-loaded tile = reference) ----
        float mx = sc[0];
        #pragma unroll
        for (int i = 1; i < NITER; i++) mx = fmaxf(mx, sc[i]);
        mx = fmaxf(mx, __shfl_xor_sync(FULL, mx, 8));
        mx = fmaxf(mx, __shfl_xor_sync(FULL, mx, 16));

        float e[NITER];
        float s = 0.f;
        #pragma unroll
        for (int i = 0; i < NITER; i++) { e[i] = __expf(sc[i] - mx); s += e[i]; }
        s += __shfl_xor_sync(FULL, s, 8);
        s += __shfl_xor_sync(FULL, s, 16);
        float inv = __frcp_rn(s);

        // ---- Weighted sum (weights lane-local; v=0 for skipped rows) ----
        float4 o = make_float4(0.f, 0.f, 0.f, 0.f);
        #pragma unroll
        for (int i = 0; i < NITER; i++) {
            float a = e[i] * inv;
            o.x = fmaf(a, v[i].x, o.x);
            o.y = fmaf(a, v[i].y, o.y);
            o.z = fmaf(a, v[i].z, o.z);
            o.w = fmaf(a, v[i].w, o.w);
        }

        // Reduce partial outputs across the 4 sub groups.
        #pragma unroll
        for (int off = 8; off <= 16; off <<= 1) {
            o.x += __shfl_xor_sync(FULL, o.x, off);
            o.y += __shfl_xor_sync(FULL, o.y, off);
            o.z += __shfl_xor_sync(FULL, o.z, off);
            o.w += __shfl_xor_sync(FULL, o.w, off);
        }

        if (sub == 0) {
            float4 ci = __ldg((const float4*)(cur_item + (long long)tile_id * DD) + quad);
            float4 r = make_float4(o.x + ci.x, o.y + ci.y, o.z + ci.z, o.w + ci.w);
            ((float4*)(out + (long long)tile_id * DD))[quad] = r;
        }

        // rotate prefetched mask into place
        m0 = nm0;
        m1 = nm1;
        tile_id = next_id;
    }
}

extern "C" void kernel_launch(void* const* d_in, const int* in_sizes, int n_in,
                              void* d_out, int out_size) {
    // Select inputs by element count (robust to ordering):
    const float* cur_user = nullptr;
    const float* sim_user = nullptr;
    const float* cur_item = nullptr;
    const int*   mask     = nullptr;
    for (int i = 0; i < n_in; i++) {
        switch (in_sizes[i]) {
            case 16384:     cur_user = (const float*)d_in[i]; break;
            case 163840000: sim_user = (const float*)d_in[i]; break;
            case 3276800:   cur_item = (const float*)d_in[i]; break;
            case 5120000:   mask     = (const int*)d_in[i];   break;
        }
    }
    float* out = (float*)d_out;

    int total_warps = (BB * SS) / TPW;      // 25600 persistent warps, 4 tiles each
    int threads = 256;
    int blocks = (total_warps * 32 + threads - 1) / threads;  // 3200
    DIB_attn_kernel<<<blocks, threads>>>(cur_user, sim_user, cur_item, mask, out);
}